// round 13
// baseline (speedup 1.0000x reference)
#include <cuda_runtime.h>
#include <cstdint>

// VQ-VAE quantizer — bit-faithful fp32 argmin, FFMA2 mainloop,
// persistent 148-CTA scheduling over 1024 units of 128 rows (1.2% imbalance).
// out f32: [ loss(1) | quantized NCHW (8388608) | idx (131072) ]

#define TPB 128
#define UROWS 128
#define NUNITS 1024
#define NSM 148
#define DIM 64
#define KCODES 1024
#define NROWS (32*64*64)
#define QELEMS (NROWS*DIM)

// smem words
#define XS_W 0                 // 128*68 = 8704
#define ES_W 8704              // 2 bufs x 4096
#define SES_W 16896            // 1024
#define RED_W 17920            // 128
#define MS_W 18048
#define SMEM_B ((MS_W + 4) * 4)

__device__ float g_se[KCODES];
__device__ float g_pair[KCODES/2][128];   // [k>>1][c*2 + (k&1)] = cb[k][c]
__device__ float g_losspart[NUNITS];
__device__ int g_ctr;

typedef unsigned long long u64;
__device__ __forceinline__ uint32_t s2u(const void* p){
    uint32_t a; asm("{ .reg .u64 t; cvta.to.shared.u64 t, %1; cvt.u32.u64 %0, t; }":"=r"(a):"l"(p)); return a;
}
__device__ __forceinline__ void fma2(u64& acc, u64 a, u64 b) {
    asm("fma.rn.f32x2 %0, %1, %2, %3;" : "=l"(acc) : "l"(a), "l"(b), "l"(acc));
}
__device__ __forceinline__ u64 bcast2(float x) {
    u64 d; unsigned r = __float_as_uint(x);
    asm("mov.b64 %0, {%1,%1};" : "=l"(d) : "r"(r));
    return d;
}
__device__ __forceinline__ void unpack2(u64 v, float& lo, float& hi) {
    unsigned a, b;
    asm("mov.b64 {%0,%1}, %2;" : "=r"(a), "=r"(b) : "l"(v));
    lo = __uint_as_float(a); hi = __uint_as_float(b);
}
#define CPA16(dst, src) asm volatile("cp.async.cg.shared.global [%0], [%1], 16;"::"r"(dst),"l"(src):"memory")
#define CPCOMMIT()      asm volatile("cp.async.commit_group;":::"memory")
#define CPWAIT(n)       asm volatile("cp.async.wait_group %0;"::"n"(n):"memory")

// ---------------- prep: coalesced pair repack + se + ctr reset -------------
__global__ void vq_prep(const float* __restrict__ cb) {
    int t = blockIdx.x * blockDim.x + threadIdx.x;
    if (t == 0) g_ctr = 0;
    if (t < 8192) {                       // repack: 512 pairs x 16 c-quads
        int p = t >> 4, q = t & 15;
        float4 a = *reinterpret_cast<const float4*>(cb + (2*p)   * DIM + q*4);
        float4 b = *reinterpret_cast<const float4*>(cb + (2*p+1) * DIM + q*4);
        float4* dst = reinterpret_cast<float4*>(&g_pair[p][q*8]);
        dst[0] = make_float4(a.x, b.x, a.y, b.y);
        dst[1] = make_float4(a.z, b.z, a.w, b.w);
    } else if (t < 9216) {                // se, sequential fmaf chain
        int k = t - 8192;
        const float* r = cb + k * DIM;
        float s = 0.f;
#pragma unroll
        for (int c = 0; c < DIM; ++c) s = fmaf(r[c], r[c], s);
        g_se[k] = s;
    }
}

// ---------------- persistent main ------------------------------------------
__global__ __launch_bounds__(TPB, 1) void vq_main(const float* __restrict__ x,
                                                  const float* __restrict__ cb,
                                                  float* __restrict__ out) {
    extern __shared__ float sm[];
    const uint32_t sb = s2u(sm);
    const int tid = threadIdx.x;
    int* ms = (int*)(sm + MS_W);
    float* red = sm + RED_W;
    float* qout = out + 1;
    float* iout = out + 1 + QELEMS;

#define BLOAD(ch) do { int _c = (ch); int _bf = _c & 1; \
    for (int i = tid; i < 1024; i += TPB) \
        CPA16(sb + 4*(ES_W + _bf*4096) + i*16, (const char*)g_pair + _c*16384 + i*16); \
    CPCOMMIT(); } while (0)

    for (int i = tid; i < KCODES; i += TPB) sm[SES_W + i] = g_se[i];
    BLOAD(0);
    BLOAD(1);

    if (tid == 0) ms[0] = atomicAdd(&g_ctr, 1);
    __syncthreads();
    int u = ms[0];

    while (u < NUNITS) {
        const int n0 = u * UROWS;
        const int b = n0 >> 12, off = n0 & 4095;
        const float* xb = x + (size_t)b*262144 + off;

        // x tile: [r][c] stride 68 (coalesced float4 over rows)
        for (int i = tid; i < 2048; i += TPB) {
            int c = i >> 5, r4 = (i & 31) << 2;
            float4 v = *reinterpret_cast<const float4*>(xb + c*4096 + r4);
            sm[XS_W + (r4+0)*68 + c] = v.x;
            sm[XS_W + (r4+1)*68 + c] = v.y;
            sm[XS_W + (r4+2)*68 + c] = v.z;
            sm[XS_W + (r4+3)*68 + c] = v.w;
        }
        __syncthreads();

        const float* xr = sm + XS_W + tid*68;
        float sx = 0.f;
#pragma unroll
        for (int c = 0; c < DIM; ++c) sx = fmaf(xr[c], xr[c], sx);

        float best = 3e38f; int bidx = 0;

        for (int cc = 0; cc < 16; ++cc) {
            CPWAIT(1);
            __syncthreads();
            const float* eb = sm + ES_W + (cc & 1)*4096;

#pragma unroll 1
            for (int kg = 0; kg < 2; ++kg) {
                u64 acc[16];
#pragma unroll
                for (int p = 0; p < 16; ++p) acc[p] = 0ull;

#pragma unroll 4
                for (int c4 = 0; c4 < 16; ++c4) {
                    float4 xa = *reinterpret_cast<const float4*>(xr + c4*4);
                    u64 a0 = bcast2(xa.x), a1 = bcast2(xa.y);
                    u64 a2 = bcast2(xa.z), a3 = bcast2(xa.w);
#pragma unroll
                    for (int p = 0; p < 16; ++p) {
                        const u64* ep = reinterpret_cast<const u64*>(eb + (kg*16+p)*128 + c4*8);
                        ulonglong2 eA = *reinterpret_cast<const ulonglong2*>(ep);
                        ulonglong2 eB = *reinterpret_cast<const ulonglong2*>(ep + 2);
                        fma2(acc[p], a0, eA.x); fma2(acc[p], a1, eA.y);
                        fma2(acc[p], a2, eB.x); fma2(acc[p], a3, eB.y);
                    }
                }
#pragma unroll
                for (int p = 0; p < 16; ++p) {
                    int ke = cc*64 + (kg*16 + p)*2;
                    float2 se2 = *reinterpret_cast<const float2*>(sm + SES_W + ke);
                    float Pe, Po;
                    unpack2(acc[p], Pe, Po);
                    float de = __fadd_rn(__fadd_rn(sx, se2.x), __fmul_rn(-2.0f, Pe));
                    float dd = __fadd_rn(__fadd_rn(sx, se2.y), __fmul_rn(-2.0f, Po));
                    if (de < best) { best = de; bidx = ke; }
                    if (dd < best) { best = dd; bidx = ke + 1; }
                }
            }
            __syncthreads();
            BLOAD((cc + 2) & 15);   // periodic stream: chunks identical per unit
        }

        // epilogue: gather q (NCHW coalesced per c), idx, per-unit loss
        const float* e = cb + bidx*DIM;
        float* q = qout + (size_t)b*262144 + off + tid;
        float lsum = 0.f;
#pragma unroll
        for (int c = 0; c < DIM; ++c) {
            float ec = __ldg(e + c);
            float d = ec - xr[c];
            lsum = fmaf(d, d, lsum);
            q[c*4096] = ec;
        }
        iout[n0 + tid] = (float)bidx;

        red[tid] = lsum;
        __syncthreads();
#pragma unroll
        for (int s = TPB/2; s > 0; s >>= 1) {
            if (tid < s) red[tid] += red[tid + s];
            __syncthreads();
        }
        if (tid == 0) {
            g_losspart[u] = red[0];
            ms[0] = atomicAdd(&g_ctr, 1);
        }
        __syncthreads();
        u = ms[0];
    }
    CPWAIT(0);
}

// ---------------- loss: deterministic sum over 1024 unit partials ----------
__global__ void vq_loss(float* __restrict__ out) {
    __shared__ float red[512];
    int tid = threadIdx.x;
    red[tid] = g_losspart[tid] + g_losspart[tid + 512];
    __syncthreads();
    for (int s = 256; s > 0; s >>= 1) {
        if (tid < s) red[tid] += red[tid + s];
        __syncthreads();
    }
    if (tid == 0) out[0] = red[0] * (1.25f / (float)QELEMS);
}

extern "C" void kernel_launch(void* const* d_in, const int* in_sizes, int n_in,
                              void* d_out, int out_size) {
    const float* x  = (const float*)d_in[0];
    const float* cb = (const float*)d_in[1];
    float* out = (float*)d_out;
    cudaFuncSetAttribute(vq_main, cudaFuncAttributeMaxDynamicSharedMemorySize, SMEM_B);
    vq_prep<<<36, 256>>>(cb);
    vq_main<<<NSM, TPB, SMEM_B>>>(x, cb, out);
    vq_loss<<<1, 512>>>(out);
}

// round 14
// speedup vs baseline: 1.3323x; 1.3323x over previous
#include <cuda_runtime.h>
#include <cstdint>

// VQ-VAE quantizer — bit-faithful fp32 argmin, FFMA2 mainloop.
// R14: persistent 148 CTAs over 1024 units = (512-row tile, 256-code quarter);
// R8 inner shape (4 rows/thread). Merge kernel combines quarters + outputs.
// out f32: [ loss(1) | quantized NCHW (8388608) | idx (131072) ]

#define TPB 128
#define TROWS 512
#define NUNITS 1024
#define NSM 148
#define DIM 64
#define KCODES 1024
#define NROWS (32*64*64)
#define QELEMS (NROWS*DIM)

// smem words
#define XS_W 0                 // 512*68 = 34816
#define ES_W 34816             // 2 bufs x 4096
#define SES_W 43008            // 1024
#define MS_W 44032
#define SMEM_B ((MS_W + 4) * 4)

__device__ float g_se[KCODES];
__device__ float g_pair[KCODES/2][128];   // [k>>1][c*2 + (k&1)] = cb[k][c]
__device__ float2 g_q[4][NROWS];          // per-quarter {d, k}
__device__ float g_losspart[512];
__device__ int g_ctr;

typedef unsigned long long u64;
__device__ __forceinline__ uint32_t s2u(const void* p){
    uint32_t a; asm("{ .reg .u64 t; cvta.to.shared.u64 t, %1; cvt.u32.u64 %0, t; }":"=r"(a):"l"(p)); return a;
}
__device__ __forceinline__ void fma2(u64& acc, u64 a, u64 b) {
    asm("fma.rn.f32x2 %0, %1, %2, %3;" : "=l"(acc) : "l"(a), "l"(b), "l"(acc));
}
__device__ __forceinline__ u64 bcast2(float x) {
    u64 d; unsigned r = __float_as_uint(x);
    asm("mov.b64 %0, {%1,%1};" : "=l"(d) : "r"(r));
    return d;
}
__device__ __forceinline__ void unpack2(u64 v, float& lo, float& hi) {
    unsigned a, b;
    asm("mov.b64 {%0,%1}, %2;" : "=r"(a), "=r"(b) : "l"(v));
    lo = __uint_as_float(a); hi = __uint_as_float(b);
}
#define CPA16(dst, src) asm volatile("cp.async.cg.shared.global [%0], [%1], 16;"::"r"(dst),"l"(src):"memory")
#define CPCOMMIT()      asm volatile("cp.async.commit_group;":::"memory")
#define CPWAIT(n)       asm volatile("cp.async.wait_group %0;"::"n"(n):"memory")

// ---------------- prep: repack + se + ctr --------------------------------
__global__ void vq_prep(const float* __restrict__ cb) {
    int t = blockIdx.x * blockDim.x + threadIdx.x;
    if (t == 0) g_ctr = NSM;
    if (t < 8192) {                        // pair repack, coalesced
        int p = t >> 4, q = t & 15;
        float4 a = *reinterpret_cast<const float4*>(cb + (2*p)   * DIM + q*4);
        float4 b = *reinterpret_cast<const float4*>(cb + (2*p+1) * DIM + q*4);
        float4* dst = reinterpret_cast<float4*>(&g_pair[p][q*8]);
        dst[0] = make_float4(a.x, b.x, a.y, b.y);
        dst[1] = make_float4(a.z, b.z, a.w, b.w);
    } else if (t < 9216) {                 // se, sequential fmaf chain
        int k = t - 8192;
        const float* r = cb + k * DIM;
        float s = 0.f;
#pragma unroll
        for (int c = 0; c < DIM; ++c) s = fmaf(r[c], r[c], s);
        g_se[k] = s;
    }
}

// ---------------- persistent main -----------------------------------------
__global__ __launch_bounds__(TPB, 1) void vq_main(const float* __restrict__ x) {
    extern __shared__ float sm[];
    const uint32_t sb = s2u(sm);
    const int tid = threadIdx.x;
    int* ms = (int*)(sm + MS_W);

#define BLOAD(ch) do { int _c = (ch); int _bf = _c & 1; \
    for (int i = tid; i < 1024; i += TPB) \
        CPA16(sb + 4*(ES_W + _bf*4096) + i*16, (const char*)g_pair + _c*16384 + i*16); \
    CPCOMMIT(); } while (0)

    for (int i = tid; i < KCODES; i += TPB) sm[SES_W + i] = g_se[i];

    int u = blockIdx.x;
    while (u < NUNITS) {
        const int tile = u >> 2, q = u & 3;
        const int n0 = tile * TROWS;
        const int b = n0 >> 12, off = n0 & 4095;
        const float* xb = x + (size_t)b*262144 + off;

        BLOAD(q*4);
        BLOAD(q*4 + 1);

        // x tile -> smem [r][c] stride 68 (coalesced float4 over rows)
        for (int i = tid; i < 8192; i += TPB) {
            int c = i >> 7, r4 = (i & 127) << 2;
            float4 v = *reinterpret_cast<const float4*>(xb + c*4096 + r4);
            sm[XS_W + (r4+0)*68 + c] = v.x;
            sm[XS_W + (r4+1)*68 + c] = v.y;
            sm[XS_W + (r4+2)*68 + c] = v.z;
            sm[XS_W + (r4+3)*68 + c] = v.w;
        }
        __syncthreads();

        float sx[4];
#pragma unroll
        for (int j = 0; j < 4; ++j) {
            const float* xr = sm + XS_W + (tid + j*TPB)*68;
            float s = 0.f;
#pragma unroll
            for (int c = 0; c < DIM; ++c) s = fmaf(xr[c], xr[c], s);
            sx[j] = s;
        }

        float best[4] = {3e38f, 3e38f, 3e38f, 3e38f};
        int bidx[4] = {0, 0, 0, 0};

        for (int cc = 0; cc < 4; ++cc) {
            if (cc < 3) { CPWAIT(1); } else { CPWAIT(0); }
            __syncthreads();
            const float* eb = sm + ES_W + (cc & 1)*4096;

            for (int kg = 0; kg < 4; ++kg) {
                u64 acc[4][8];
#pragma unroll
                for (int j = 0; j < 4; ++j)
#pragma unroll
                    for (int p = 0; p < 8; ++p) acc[j][p] = 0ull;

#pragma unroll 4
                for (int c4 = 0; c4 < 16; ++c4) {
                    u64 a[4][4];
#pragma unroll
                    for (int j = 0; j < 4; ++j) {
                        float4 xa = *reinterpret_cast<const float4*>(
                            sm + XS_W + (tid + j*TPB)*68 + c4*4);
                        a[j][0] = bcast2(xa.x); a[j][1] = bcast2(xa.y);
                        a[j][2] = bcast2(xa.z); a[j][3] = bcast2(xa.w);
                    }
#pragma unroll
                    for (int p = 0; p < 8; ++p) {
                        const u64* ep = reinterpret_cast<const u64*>(eb + (kg*8+p)*128 + c4*8);
                        ulonglong2 eA = *reinterpret_cast<const ulonglong2*>(ep);
                        ulonglong2 eB = *reinterpret_cast<const ulonglong2*>(ep + 2);
#pragma unroll
                        for (int j = 0; j < 4; ++j) {
                            fma2(acc[j][p], a[j][0], eA.x); fma2(acc[j][p], a[j][1], eA.y);
                            fma2(acc[j][p], a[j][2], eB.x); fma2(acc[j][p], a[j][3], eB.y);
                        }
                    }
                }
#pragma unroll
                for (int p = 0; p < 8; ++p) {
                    int ke = q*256 + cc*64 + kg*16 + 2*p;
                    float2 se2 = *reinterpret_cast<const float2*>(sm + SES_W + ke);
#pragma unroll
                    for (int j = 0; j < 4; ++j) {
                        float Pe, Po;
                        unpack2(acc[j][p], Pe, Po);
                        float de = __fadd_rn(__fadd_rn(sx[j], se2.x), __fmul_rn(-2.0f, Pe));
                        float dd = __fadd_rn(__fadd_rn(sx[j], se2.y), __fmul_rn(-2.0f, Po));
                        if (de < best[j]) { best[j] = de; bidx[j] = ke; }
                        if (dd < best[j]) { best[j] = dd; bidx[j] = ke + 1; }
                    }
                }
            }
            __syncthreads();
            if (cc < 2) BLOAD(q*4 + cc + 2);
        }

#pragma unroll
        for (int j = 0; j < 4; ++j)
            g_q[q][n0 + tid + j*TPB] = make_float2(best[j], (float)bidx[j]);

        if (tid == 0) ms[0] = atomicAdd(&g_ctr, 1);
        __syncthreads();
        u = ms[0];
    }
}

// ---------------- merge: quarters -> winner, gather, idx, loss -------------
__global__ __launch_bounds__(256) void vq_merge(const float* __restrict__ x,
                                                const float* __restrict__ cb,
                                                float* __restrict__ out) {
    __shared__ float red[256];
    const int tid = threadIdx.x;
    const int n = blockIdx.x*256 + tid;

    float2 w = g_q[0][n];
#pragma unroll
    for (int q = 1; q < 4; ++q) {
        float2 h = g_q[q][n];
        if (h.x < w.x) w = h;          // strict < : tie -> lower quarter/k
    }
    int code = (int)w.y;

    const int b = n >> 12, hw = n & 4095;
    const float* xr = x + (size_t)b*262144 + hw;
    const float* e  = cb + code*DIM;
    float* qo = out + 1 + (size_t)b*262144 + hw;
    float lsum = 0.f;
#pragma unroll
    for (int c = 0; c < DIM; ++c) {
        float ec = __ldg(e + c);
        float d = ec - xr[c*4096];
        lsum = fmaf(d, d, lsum);
        qo[c*4096] = ec;
    }
    out[1 + QELEMS + n] = (float)code;

    red[tid] = lsum;
    __syncthreads();
#pragma unroll
    for (int s = 128; s > 0; s >>= 1) {
        if (tid < s) red[tid] += red[tid + s];
        __syncthreads();
    }
    if (tid == 0) g_losspart[blockIdx.x] = red[0];
}

__global__ void vq_loss(float* __restrict__ out) {
    __shared__ float red[512];
    int tid = threadIdx.x;
    red[tid] = g_losspart[tid];
    __syncthreads();
    for (int s = 256; s > 0; s >>= 1) {
        if (tid < s) red[tid] += red[tid + s];
        __syncthreads();
    }
    if (tid == 0) out[0] = red[0] * (1.25f / (float)QELEMS);
}

extern "C" void kernel_launch(void* const* d_in, const int* in_sizes, int n_in,
                              void* d_out, int out_size) {
    const float* x  = (const float*)d_in[0];
    const float* cb = (const float*)d_in[1];
    float* out = (float*)d_out;
    cudaFuncSetAttribute(vq_main, cudaFuncAttributeMaxDynamicSharedMemorySize, SMEM_B);
    vq_prep<<<36, 256>>>(cb);
    vq_main<<<NSM, TPB, SMEM_B>>>(x);
    vq_merge<<<NROWS/256, 256>>>(x, cb, out);
    vq_loss<<<1, 512>>>(out);
}